// round 3
// baseline (speedup 1.0000x reference)
#include <cuda_runtime.h>

// Canny magnitude, fully fused: gray -> 5x5 separable gaussian (reflect pad)
// -> sobel (edge pad) -> magnitude -> 8-dir NMS (zero pad) -> mag * is_max.
// Input  (16, 3, 512, 512) f32, output (16, 1, 512, 512) f32.

#define H_IMG 512
#define W_IMG 512
#define B_IMG 16

#define TX 64           // output tile width
#define TY 32           // output tile height
#define NT 256          // threads per block

#define GW (TX + 8)     // 72  gray tile width   (halo 4)
#define GH (TY + 8)     // 40  gray tile height
#define HW (TX + 4)     // 68  h-blur tile width (halo 2)
#define BH (TY + 4)     // 36  blur tile height
#define MW (TX + 2)     // 66  magnitude tile width (halo 1)
#define MH (TY + 2)     // 34  magnitude tile height

// NMS neighbor linear offsets in the magnitude tile (stride MW=66):
// offs i -> (dy,dx): (0,1)(-1,1)(-1,0)(-1,-1)(0,-1)(1,-1)(1,0)(1,1)
__constant__ int c_nms_off[8] = { 1, -65, -66, -67, -1, 65, 66, 67 };

__device__ __forceinline__ int reflect_idx(int i, int n) {
    // valid for i in [-(n-1), 2n-2]; we only need [-4, n+3]
    if (i < 0) i = -i;
    if (i >= n) i = 2 * n - 2 - i;
    return i;
}

__global__ void __launch_bounds__(NT)
canny_fused_kernel(const float* __restrict__ in, float* __restrict__ out) {
    __shared__ float s_gray[GH][GW];     // 40x72
    __shared__ float s_htmp[GH][HW];     // 40x68
    __shared__ float s_blur[BH][HW];     // 36x68
    __shared__ float s_mag [MH * MW];    // 34x66 (flat for NMS offset math)

    const int tid = threadIdx.x;
    const int x0  = blockIdx.x * TX;
    const int y0  = blockIdx.y * TY;
    const int b   = blockIdx.z;

    const float* base = in + (size_t)b * 3 * H_IMG * W_IMG;

    // ---- Phase 1: grayscale with reflect-padded halo 4 ----
    // gray = 0.5*(0.299*(r+1) + 0.587*(g+1) + 0.114*(b+1))
    #pragma unroll 1
    for (int i = tid; i < GH * GW; i += NT) {
        int r = i / GW, c = i % GW;
        int yy = reflect_idx(y0 - 4 + r, H_IMG);
        int xx = reflect_idx(x0 - 4 + c, W_IMG);
        int off = yy * W_IMG + xx;
        float rc = base[off];
        float gc = base[H_IMG * W_IMG + off];
        float bc = base[2 * H_IMG * W_IMG + off];
        s_gray[r][c] = 0.5f * (0.299f * (rc + 1.0f) +
                               0.587f * (gc + 1.0f) +
                               0.114f * (bc + 1.0f));
    }
    __syncthreads();

    // Gaussian (ksize=5, sigma=1), normalized
    const float w0 = 0.054488684548643f;
    const float w1 = 0.244201342003233f;
    const float w2 = 0.402619946896247f;

    // ---- Phase 2: horizontal blur ----
    #pragma unroll 1
    for (int i = tid; i < GH * HW; i += NT) {
        int r = i / HW, c = i % HW;
        s_htmp[r][c] = w0 * (s_gray[r][c]     + s_gray[r][c + 4]) +
                       w1 * (s_gray[r][c + 1] + s_gray[r][c + 3]) +
                       w2 *  s_gray[r][c + 2];
    }
    __syncthreads();

    // ---- Phase 3: vertical blur ----
    #pragma unroll 1
    for (int i = tid; i < BH * HW; i += NT) {
        int r = i / HW, c = i % HW;
        s_blur[r][c] = w0 * (s_htmp[r][c]     + s_htmp[r + 4][c]) +
                       w1 * (s_htmp[r + 1][c] + s_htmp[r + 3][c]) +
                       w2 *  s_htmp[r + 2][c];
    }
    __syncthreads();

    // ---- Phase 4: sobel magnitude on halo-1 region (zero outside image) ----
    #pragma unroll 1
    for (int i = tid; i < MH * MW; i += NT) {
        int r = i / MW, c = i % MW;
        int my = y0 - 1 + r;
        int mx = x0 - 1 + c;
        float m = 0.0f;
        if (my >= 0 && my < H_IMG && mx >= 0 && mx < W_IMG) {
            // blur tile coord of (my,mx) is (r+1, c+1); edge-clamp neighbors
            int iy0 = max(my - 1, 0)         - (y0 - 2);
            int iy1 = r + 1;
            int iy2 = min(my + 1, H_IMG - 1) - (y0 - 2);
            int ix0 = max(mx - 1, 0)         - (x0 - 2);
            int ix1 = c + 1;
            int ix2 = min(mx + 1, W_IMG - 1) - (x0 - 2);
            float b00 = s_blur[iy0][ix0], b01 = s_blur[iy0][ix1], b02 = s_blur[iy0][ix2];
            float b10 = s_blur[iy1][ix0],                         b12 = s_blur[iy1][ix2];
            float b20 = s_blur[iy2][ix0], b21 = s_blur[iy2][ix1], b22 = s_blur[iy2][ix2];
            float gx = (b02 - b00) + 2.0f * (b12 - b10) + (b22 - b20);
            float gy = (b20 - b00) + 2.0f * (b21 - b01) + (b22 - b02);
            m = sqrtf(gx * gx + gy * gy + 1e-6f);
        }
        s_mag[r * MW + c] = m;
    }
    __syncthreads();

    // ---- Phase 5: angle octant + NMS + write ----
    #pragma unroll 1
    for (int i = tid; i < TY * TX; i += NT) {
        int r = i >> 6;        // i / TX   (TX = 64)
        int c = i & (TX - 1);  // i % TX
        int my = y0 + r;
        int mx = x0 + c;

        // recompute sobel at center (edge-clamped)
        int iy0 = max(my - 1, 0)         - (y0 - 2);
        int iy1 = r + 2;
        int iy2 = min(my + 1, H_IMG - 1) - (y0 - 2);
        int ix0 = max(mx - 1, 0)         - (x0 - 2);
        int ix1 = c + 2;
        int ix2 = min(mx + 1, W_IMG - 1) - (x0 - 2);
        float b00 = s_blur[iy0][ix0], b01 = s_blur[iy0][ix1], b02 = s_blur[iy0][ix2];
        float b10 = s_blur[iy1][ix0],                         b12 = s_blur[iy1][ix2];
        float b20 = s_blur[iy2][ix0], b21 = s_blur[iy2][ix1], b22 = s_blur[iy2][ix2];
        float gx = (b02 - b00) + 2.0f * (b12 - b10) + (b22 - b20);
        float gy = (b20 - b00) + 2.0f * (b21 - b01) + (b22 - b02);

        // octant: round(rad2deg(atan2)/45); idx in [-4,4]; python %8 == &7 here
        float deg = atan2f(gy, gx) * 57.29577951308232f;
        int idx = __float2int_rn(deg * (1.0f / 45.0f)) & 7;

        int lin = (r + 1) * MW + (c + 1);
        float mc = s_mag[lin];
        int d = c_nms_off[idx];          // opposite dir (idx+4)&7 is exactly -d
        float sp = mc - s_mag[lin + d];
        float sn = mc - s_mag[lin - d];
        float res = (fminf(sp, sn) > 0.0f) ? mc : 0.0f;

        out[((size_t)b * H_IMG + my) * W_IMG + mx] = res;
    }
}

extern "C" void kernel_launch(void* const* d_in, const int* in_sizes, int n_in,
                              void* d_out, int out_size) {
    const float* in = (const float*)d_in[0];
    float* out = (float*)d_out;
    dim3 grid(W_IMG / TX, H_IMG / TY, B_IMG);   // (8, 16, 16)
    canny_fused_kernel<<<grid, NT>>>(in, out);
}

// round 7
// speedup vs baseline: 1.1556x; 1.1556x over previous
#include <cuda_runtime.h>
#include <stdint.h>

// Canny magnitude, fully fused, ALU-optimized:
// gray -> 5x5 separable gaussian (reflect pad) -> sobel (edge pad)
// -> magnitude -> comparison-based octant -> 8-dir NMS (zero pad) -> mag*is_max
// Input (16,3,512,512) f32, output (16,1,512,512) f32.

#define H_IMG 512
#define W_IMG 512
#define B_IMG 16
#define PLANE (H_IMG * W_IMG)

#define TX 64
#define TY 32

#define GW (TX + 8)     // 72 gray width  (halo 4)
#define GH (TY + 8)     // 40 gray height
#define HW (TX + 4)     // 68 h-blur width (halo 2)
#define BH (TY + 4)     // 36 blur height
#define MW (TX + 2)     // 66 mag width   (halo 1)
#define MH (TY + 2)     // 34 mag height

// idx -> linear NMS offset in mag tile (stride MW=66):
// (0,1)(-1,1)(-1,0)(-1,-1)(0,-1)(1,-1)(1,0)(1,1)
__constant__ int c_nms_off[8] = { 1, -65, -66, -67, -1, 65, 66, 67 };

__device__ __forceinline__ int reflect_idx(int i, int n) {
    if (i < 0) i = -i;
    if (i >= n) i = 2 * n - 2 - i;
    return i;
}

__device__ __forceinline__ int octant(float gx, float gy) {
    // round(atan2(gy,gx)/45deg) mod 8 via comparisons
    float ax = fabsf(gx), ay = fabsf(gy);
    int o = (ay > 0.4142135623730950f * ax) + (ay > 2.4142135623730950f * ax);
    if (gx < 0.0f) return (gy < 0.0f) ? (4 + o) : (4 - o);
    else           return (gy < 0.0f) ? ((8 - o) & 7) : o;
}

__global__ void __launch_bounds__(256)
canny_fused_kernel(const float* __restrict__ in, float* __restrict__ out) {
    __shared__ float sA[GH * GW];   // gray; later: magnitude (MH*MW floats)
    __shared__ float sB[GH * HW];   // h-blur; later: nms offsets (int8, MH*MW)
    __shared__ float sC[BH * HW];   // blurred

    float*  sM = sA;
    int8_t* sD = (int8_t*)sB;       // int8_t: plain char is UNSIGNED on aarch64!

    const int tx = threadIdx.x;     // 0..31
    const int ty = threadIdx.y;     // 0..7
    const int x0 = blockIdx.x * TX;
    const int y0 = blockIdx.y * TY;
    const int b  = blockIdx.z;

    const float* base = in + (size_t)b * 3 * PLANE;

    const bool interior = (x0 >= 4) && (x0 + TX + 4 <= W_IMG) &&
                          (y0 >= 4) && (y0 + TY + 4 <= H_IMG);

    // ---- Phase 1: grayscale into sA (GH x GW, halo 4) ----
    // gray = 0.1495*r + 0.2935*g + 0.057*b + 0.5
    if (interior) {
        const float* p = base + (y0 - 4) * W_IMG + (x0 - 4);
        #pragma unroll
        for (int rr = 0; rr < 5; rr++) {
            const int r = ty + rr * 8;
            const float* prow = p + r * W_IMG;
            #pragma unroll
            for (int k = 0; k < 3; k++) {
                const int c = tx + k * 32;
                if (c < GW) {
                    float rc = prow[c];
                    float gc = prow[c + PLANE];
                    float bc = prow[c + 2 * PLANE];
                    sA[r * GW + c] = fmaf(0.1495f, rc,
                                     fmaf(0.2935f, gc,
                                     fmaf(0.057f,  bc, 0.5f)));
                }
            }
        }
    } else {
        #pragma unroll
        for (int rr = 0; rr < 5; rr++) {
            const int r = ty + rr * 8;
            const int yy = reflect_idx(y0 - 4 + r, H_IMG) * W_IMG;
            #pragma unroll
            for (int k = 0; k < 3; k++) {
                const int c = tx + k * 32;
                if (c < GW) {
                    const int off = yy + reflect_idx(x0 - 4 + c, W_IMG);
                    float rc = base[off];
                    float gc = base[off + PLANE];
                    float bc = base[off + 2 * PLANE];
                    sA[r * GW + c] = fmaf(0.1495f, rc,
                                     fmaf(0.2935f, gc,
                                     fmaf(0.057f,  bc, 0.5f)));
                }
            }
        }
    }
    __syncthreads();

    // Gaussian (ksize=5, sigma=1), normalized
    const float w0 = 0.054488684548643f;
    const float w1 = 0.244201342003233f;
    const float w2 = 0.402619946896247f;

    // ---- Phase 2: horizontal blur sA -> sB (GH x HW) ----
    #pragma unroll
    for (int rr = 0; rr < 5; rr++) {
        const int r = ty + rr * 8;
        const float* g = &sA[r * GW];
        #pragma unroll
        for (int k = 0; k < 3; k++) {
            const int c = tx + k * 32;
            if (c < HW) {
                sB[r * HW + c] = w0 * (g[c]     + g[c + 4]) +
                                 w1 * (g[c + 1] + g[c + 3]) +
                                 w2 *  g[c + 2];
            }
        }
    }
    __syncthreads();

    // ---- Phase 3: vertical blur sB -> sC (BH x HW) ----
    #pragma unroll
    for (int rr = 0; rr < 5; rr++) {
        const int r = ty + rr * 8;
        if (r < BH) {
            #pragma unroll
            for (int k = 0; k < 3; k++) {
                const int c = tx + k * 32;
                if (c < HW) {
                    const int i = r * HW + c;
                    sC[i] = w0 * (sB[i]          + sB[i + 4 * HW]) +
                            w1 * (sB[i + HW]     + sB[i + 3 * HW]) +
                            w2 *  sB[i + 2 * HW];
                }
            }
        }
    }
    __syncthreads();

    // ---- Phase 4: sobel magnitude + octant offset (MH x MW) ----
    // pixel (my,mx) = (y0-1+r, x0-1+c); blur tile origin (y0-2, x0-2)
    if (interior) {
        #pragma unroll
        for (int rr = 0; rr < 5; rr++) {
            const int r = ty + rr * 8;
            if (r < MH) {
                #pragma unroll
                for (int k = 0; k < 3; k++) {
                    const int c = tx + k * 32;
                    if (c < MW) {
                        const float* bp = &sC[r * HW + c];
                        float b00 = bp[0],          b01 = bp[1],          b02 = bp[2];
                        float b10 = bp[HW],                               b12 = bp[HW + 2];
                        float b20 = bp[2 * HW],     b21 = bp[2 * HW + 1], b22 = bp[2 * HW + 2];
                        float gx = (b02 - b00) + 2.0f * (b12 - b10) + (b22 - b20);
                        float gy = (b20 - b00) + 2.0f * (b21 - b01) + (b22 - b02);
                        sM[r * MW + c] = sqrtf(fmaf(gx, gx, fmaf(gy, gy, 1e-6f)));
                        sD[r * MW + c] = (int8_t)c_nms_off[octant(gx, gy)];
                    }
                }
            }
        }
    } else {
        #pragma unroll
        for (int rr = 0; rr < 5; rr++) {
            const int r = ty + rr * 8;
            if (r < MH) {
                #pragma unroll
                for (int k = 0; k < 3; k++) {
                    const int c = tx + k * 32;
                    if (c < MW) {
                        const int my = y0 - 1 + r;
                        const int mx = x0 - 1 + c;
                        float m = 0.0f;
                        int8_t dch = 1;
                        if (my >= 0 && my < H_IMG && mx >= 0 && mx < W_IMG) {
                            const int iy0 = max(my - 1, 0)         - (y0 - 2);
                            const int iy1 = r + 1;
                            const int iy2 = min(my + 1, H_IMG - 1) - (y0 - 2);
                            const int ix0 = max(mx - 1, 0)         - (x0 - 2);
                            const int ix1 = c + 1;
                            const int ix2 = min(mx + 1, W_IMG - 1) - (x0 - 2);
                            float b00 = sC[iy0 * HW + ix0], b01 = sC[iy0 * HW + ix1], b02 = sC[iy0 * HW + ix2];
                            float b10 = sC[iy1 * HW + ix0],                           b12 = sC[iy1 * HW + ix2];
                            float b20 = sC[iy2 * HW + ix0], b21 = sC[iy2 * HW + ix1], b22 = sC[iy2 * HW + ix2];
                            float gx = (b02 - b00) + 2.0f * (b12 - b10) + (b22 - b20);
                            float gy = (b20 - b00) + 2.0f * (b21 - b01) + (b22 - b02);
                            m = sqrtf(fmaf(gx, gx, fmaf(gy, gy, 1e-6f)));
                            dch = (int8_t)c_nms_off[octant(gx, gy)];
                        }
                        sM[r * MW + c] = m;
                        sD[r * MW + c] = dch;
                    }
                }
            }
        }
    }
    __syncthreads();

    // ---- Phase 5: NMS + write (TY x TX) ----
    float* orow = out + ((size_t)b * H_IMG + y0) * W_IMG + x0;
    #pragma unroll
    for (int rr = 0; rr < 4; rr++) {
        const int r = ty + rr * 8;
        #pragma unroll
        for (int k = 0; k < 2; k++) {
            const int c = tx + k * 32;
            const int lin = (r + 1) * MW + (c + 1);
            const float mc = sM[lin];
            const int d = (int)sD[lin];         // properly signed
            const float sp = mc - sM[lin + d];
            const float sn = mc - sM[lin - d];
            orow[r * W_IMG + c] = (fminf(sp, sn) > 0.0f) ? mc : 0.0f;
        }
    }
}

extern "C" void kernel_launch(void* const* d_in, const int* in_sizes, int n_in,
                              void* d_out, int out_size) {
    const float* in = (const float*)d_in[0];
    float* out = (float*)d_out;
    dim3 grid(W_IMG / TX, H_IMG / TY, B_IMG);   // (8, 16, 16)
    dim3 block(32, 8);
    canny_fused_kernel<<<grid, block>>>(in, out);
}

// round 8
// speedup vs baseline: 1.3067x; 1.1308x over previous
#include <cuda_runtime.h>
#include <stdint.h>

// Canny magnitude, fully fused + float4-vectorized shared pipeline.
// gray -> 5x5 separable gaussian (reflect) -> sobel (edge clamp) -> magnitude
// -> comparison octant -> 8-dir NMS (zero pad) -> mag * is_max
// Input (16,3,512,512) f32, output (16,1,512,512) f32.

#define H_IMG 512
#define W_IMG 512
#define PLANE (H_IMG * W_IMG)
#define TX 64
#define TY 32
#define NT 256

#define GW 72   // gray width/stride  (halo 4)  = 18 float4
#define GH 40
#define HW 68   // h-blur width/stride (halo 2) = 17 float4
#define BH 36   // blur rows
#define BW 72   // blur stride (PADDED; valid cols 0..67)
#define MH 34
#define MW 68   // mag stride (valid cols 0..65; 66,67 pad = 0)

// idx -> linear NMS offset in mag tile (stride MW=68):
// (0,1)(-1,1)(-1,0)(-1,-1)(0,-1)(1,-1)(1,0)(1,1)
__constant__ int c_nms_off[8] = { 1, -67, -68, -69, -1, 67, 68, 69 };

__device__ __forceinline__ int reflect_idx(int i, int n) {
    if (i < 0) i = -i;
    if (i >= n) i = 2 * n - 2 - i;
    return i;
}

__device__ __forceinline__ int octant(float gx, float gy) {
    // round(atan2(gy,gx)/45deg) mod 8 via comparisons
    float ax = fabsf(gx), ay = fabsf(gy);
    int o = (ay > 0.4142135623730950f * ax) + (ay > 2.4142135623730950f * ax);
    if (gx < 0.0f) return (gy < 0.0f) ? (4 + o) : (4 - o);
    else           return (gy < 0.0f) ? ((8 - o) & 7) : o;
}

__global__ void __launch_bounds__(NT)
canny_fused_kernel(const float* __restrict__ in, float* __restrict__ out) {
    __shared__ __align__(16) float sA[GH * GW];   // gray; later mag (MH*MW)
    __shared__ __align__(16) float sB[GH * HW];   // htmp; later dir bytes
    __shared__ __align__(16) float sC[BH * BW];   // blurred (padded stride)

    float*    sM  = sA;
    int8_t*   sD  = (int8_t*)sB;
    uint32_t* sDw = (uint32_t*)sB;

    const int tid = threadIdx.x;
    const int x0  = blockIdx.x * TX;
    const int y0  = blockIdx.y * TY;
    const int b   = blockIdx.z;

    const float* base = in + (size_t)b * 3 * PLANE;

    const bool interior = (x0 >= 4) && (x0 + TX + 4 <= W_IMG) &&
                          (y0 >= 4) && (y0 + TY + 4 <= H_IMG);

    // ---- Phase 1: grayscale into sA (GH x GW) ----
    // gray = 0.1495*r + 0.2935*g + 0.057*b + 0.5
    if (interior) {
        const float* p = base + (y0 - 4) * W_IMG + (x0 - 4);  // 16B aligned
        #pragma unroll 1
        for (int i = tid; i < GH * 18; i += NT) {
            int r = i / 18, c4 = (i - r * 18) * 4;
            const float* q = p + r * W_IMG + c4;
            float4 R = *(const float4*)q;
            float4 G = *(const float4*)(q + PLANE);
            float4 B = *(const float4*)(q + 2 * PLANE);
            float4 o;
            o.x = fmaf(0.1495f, R.x, fmaf(0.2935f, G.x, fmaf(0.057f, B.x, 0.5f)));
            o.y = fmaf(0.1495f, R.y, fmaf(0.2935f, G.y, fmaf(0.057f, B.y, 0.5f)));
            o.z = fmaf(0.1495f, R.z, fmaf(0.2935f, G.z, fmaf(0.057f, B.z, 0.5f)));
            o.w = fmaf(0.1495f, R.w, fmaf(0.2935f, G.w, fmaf(0.057f, B.w, 0.5f)));
            *(float4*)(sA + r * GW + c4) = o;
        }
    } else {
        #pragma unroll 1
        for (int i = tid; i < GH * 18; i += NT) {
            int r = i / 18, c4 = (i - r * 18) * 4;
            int yy = reflect_idx(y0 - 4 + r, H_IMG) * W_IMG;
            float o[4];
            #pragma unroll
            for (int j = 0; j < 4; j++) {
                int off = yy + reflect_idx(x0 - 4 + c4 + j, W_IMG);
                o[j] = fmaf(0.1495f, base[off],
                       fmaf(0.2935f, base[off + PLANE],
                       fmaf(0.057f,  base[off + 2 * PLANE], 0.5f)));
            }
            *(float4*)(sA + r * GW + c4) = make_float4(o[0], o[1], o[2], o[3]);
        }
    }
    __syncthreads();

    const float w0 = 0.054488684548643f;
    const float w1 = 0.244201342003233f;
    const float w2 = 0.402619946896247f;

    // ---- Phase 2: horizontal blur sA -> sB (GH x HW) ----
    #pragma unroll 1
    for (int i = tid; i < GH * 17; i += NT) {
        int r = i / 17, c4 = (i - r * 17) * 4;
        const float* g = sA + r * GW + c4;
        float4 a = *(const float4*)g;
        float4 c = *(const float4*)(g + 4);
        float4 o;
        o.x = w0 * (a.x + c.x) + w1 * (a.y + a.w) + w2 * a.z;
        o.y = w0 * (a.y + c.y) + w1 * (a.z + c.x) + w2 * a.w;
        o.z = w0 * (a.z + c.z) + w1 * (a.w + c.y) + w2 * c.x;
        o.w = w0 * (a.w + c.w) + w1 * (c.x + c.z) + w2 * c.y;
        *(float4*)(sB + r * HW + c4) = o;
    }
    __syncthreads();

    // ---- Phase 3: vertical blur sB -> sC (BH x BW, padded stride) ----
    #pragma unroll 1
    for (int i = tid; i < BH * 17; i += NT) {
        int r = i / 17, c4 = (i - r * 17) * 4;
        const float* h = sB + r * HW + c4;
        float4 v0 = *(const float4*)h;
        float4 v1 = *(const float4*)(h + HW);
        float4 v2 = *(const float4*)(h + 2 * HW);
        float4 v3 = *(const float4*)(h + 3 * HW);
        float4 v4 = *(const float4*)(h + 4 * HW);
        float4 o;
        o.x = w0 * (v0.x + v4.x) + w1 * (v1.x + v3.x) + w2 * v2.x;
        o.y = w0 * (v0.y + v4.y) + w1 * (v1.y + v3.y) + w2 * v2.y;
        o.z = w0 * (v0.z + v4.z) + w1 * (v1.z + v3.z) + w2 * v2.z;
        o.w = w0 * (v0.w + v4.w) + w1 * (v1.w + v3.w) + w2 * v2.w;
        *(float4*)(sC + r * BW + c4) = o;
    }
    __syncthreads();

    // ---- Phase 4: sobel magnitude + packed octant offsets (MH x MW) ----
    if (interior) {
        #pragma unroll 1
        for (int i = tid; i < MH * 17; i += NT) {
            int r = i / 17, c0 = (i - r * 17) * 4;
            const float* bp = sC + r * BW + c0;
            float t0[8], t1[8], t2[8];
            *(float4*)t0       = *(const float4*)bp;
            *(float4*)(t0 + 4) = *(const float4*)(bp + 4);
            *(float4*)t1       = *(const float4*)(bp + BW);
            *(float4*)(t1 + 4) = *(const float4*)(bp + BW + 4);
            *(float4*)t2       = *(const float4*)(bp + 2 * BW);
            *(float4*)(t2 + 4) = *(const float4*)(bp + 2 * BW + 4);
            float m[4];
            uint32_t dpack = 0;
            #pragma unroll
            for (int j = 0; j < 4; j++) {
                float gx = (t0[j+2] - t0[j]) + 2.0f * (t1[j+2] - t1[j]) + (t2[j+2] - t2[j]);
                float gy = (t2[j]   - t0[j]) + 2.0f * (t2[j+1] - t0[j+1]) + (t2[j+2] - t0[j+2]);
                float mm = sqrtf(fmaf(gx, gx, fmaf(gy, gy, 1e-6f)));
                int d = c_nms_off[octant(gx, gy)];
                if (c0 + j > 65) { mm = 0.0f; d = 1; }   // tile pad cols
                m[j] = mm;
                dpack |= ((uint32_t)(uint8_t)(int8_t)d) << (8 * j);
            }
            *(float4*)(sM + r * MW + c0) = make_float4(m[0], m[1], m[2], m[3]);
            sDw[(r * MW + c0) >> 2] = dpack;
        }
    } else {
        #pragma unroll 1
        for (int i = tid; i < MH * MW; i += NT) {
            int r = i / MW, c = i - r * MW;
            float mm = 0.0f;
            int8_t dch = 1;
            if (c <= 65) {
                int my = y0 - 1 + r;
                int mx = x0 - 1 + c;
                if (my >= 0 && my < H_IMG && mx >= 0 && mx < W_IMG) {
                    int iy0 = max(my - 1, 0)         - (y0 - 2);
                    int iy1 = r + 1;
                    int iy2 = min(my + 1, H_IMG - 1) - (y0 - 2);
                    int ix0 = max(mx - 1, 0)         - (x0 - 2);
                    int ix1 = c + 1;
                    int ix2 = min(mx + 1, W_IMG - 1) - (x0 - 2);
                    float b00 = sC[iy0*BW+ix0], b01 = sC[iy0*BW+ix1], b02 = sC[iy0*BW+ix2];
                    float b10 = sC[iy1*BW+ix0],                       b12 = sC[iy1*BW+ix2];
                    float b20 = sC[iy2*BW+ix0], b21 = sC[iy2*BW+ix1], b22 = sC[iy2*BW+ix2];
                    float gx = (b02 - b00) + 2.0f * (b12 - b10) + (b22 - b20);
                    float gy = (b20 - b00) + 2.0f * (b21 - b01) + (b22 - b02);
                    mm = sqrtf(fmaf(gx, gx, fmaf(gy, gy, 1e-6f)));
                    dch = (int8_t)c_nms_off[octant(gx, gy)];
                }
            }
            sM[i] = mm;
            sD[i] = dch;
        }
    }
    __syncthreads();

    // ---- Phase 5: NMS + vectorized write (TY x TX) ----
    float* obase = out + ((size_t)b * H_IMG + y0) * W_IMG + x0;
    #pragma unroll 1
    for (int i = tid; i < TY * 16; i += NT) {     // 512 float4 items
        int r  = i >> 4;
        int c0 = (i & 15) * 4;
        int bse = (r + 1) * MW + c0;              // 16B aligned
        float4 m0 = *(const float4*)(sM + bse);
        float4 m1 = *(const float4*)(sM + bse + 4);
        uint32_t wlo = sDw[bse >> 2];
        uint32_t whi = sDw[(bse >> 2) + 1];
        uint32_t dv  = __funnelshift_r(wlo, whi, 8);  // bytes = dirs for cols c0+1..c0+4
        float ctr[4] = { m0.y, m0.z, m0.w, m1.x };
        float res[4];
        #pragma unroll
        for (int j = 0; j < 4; j++) {
            int d = (int)(int8_t)(dv >> (8 * j));
            int lin = bse + 1 + j;
            float mc = ctr[j];
            float sp = mc - sM[lin + d];
            float sn = mc - sM[lin - d];
            res[j] = (fminf(sp, sn) > 0.0f) ? mc : 0.0f;
        }
        *(float4*)(obase + r * W_IMG + c0) = make_float4(res[0], res[1], res[2], res[3]);
    }
}

extern "C" void kernel_launch(void* const* d_in, const int* in_sizes, int n_in,
                              void* d_out, int out_size) {
    const float* in = (const float*)d_in[0];
    float* out = (float*)d_out;
    dim3 grid(W_IMG / TX, H_IMG / TY, 16);   // (8, 16, 16)
    canny_fused_kernel<<<grid, NT>>>(in, out);
}